// round 13
// baseline (speedup 1.0000x reference)
#include <cuda_runtime.h>
#include <math_constants.h>

// Problem constants (fixed by dataset): B=8, N=M=8192, 3-D points.
#define MAXB 8
#define MAXN 8192
#define MAXM 8192
#define CPB   103         // CTAs per batch (103*8 = 824 <= 148 SMs * occ 6 = 888: one wave)
#define SRCT  80          // sources per CTA tile (103*80 >= 8192; last CTA clamps indices)
#define NPP   5           // packed source-pairs per thread (10 sources / thread)

typedef unsigned long long u64;

// Static scratch (allocation-free rule).
__device__ float4       g_tpack[MAXB * MAXM];   // {x, y, z, -0.5|t|^2}
__device__ unsigned int g_tmax[MAXB * MAXM];    // encoded max-e per target (re-armed by finish)
__device__ float        g_ssum[MAXB * CPB];     // per-CTA masked source max-e sums

// ---- f32x2 packed math (FFMA2/FADD2 — PTX-only on sm_103a) --------------
__device__ __forceinline__ u64 pack2(float lo, float hi) {
    u64 r; asm("mov.b64 %0,{%1,%2};" : "=l"(r) : "f"(lo), "f"(hi)); return r;
}
__device__ __forceinline__ void unpack2(u64 v, float& lo, float& hi) {
    asm("mov.b64 {%0,%1},%2;" : "=f"(lo), "=f"(hi) : "l"(v));
}
__device__ __forceinline__ u64 fma2_(u64 a, u64 b, u64 c) {
    u64 d; asm("fma.rn.f32x2 %0,%1,%2,%3;" : "=l"(d) : "l"(a), "l"(b), "l"(c)); return d;
}
__device__ __forceinline__ u64 add2_(u64 a, u64 b) {
    u64 d; asm("add.rn.f32x2 %0,%1,%2;" : "=l"(d) : "l"(a), "l"(b)); return d;
}

// ---- monotonic float<->uint encoding (order-preserving, any sign) -------
// Note: encoded values of all representable e are > 0, so an all-zero initial
// state (static __device__ arrays start zeroed) acts as "-infinity" for
// atomicMax on the first run; finish re-arms to fenc(-inf) for every replay.
__device__ __forceinline__ unsigned fenc(float f) {
    unsigned b = __float_as_uint(f);
    return (b & 0x80000000u) ? ~b : (b | 0x80000000u);
}
__device__ __forceinline__ float fdec(unsigned k) {
    return __uint_as_float((k & 0x80000000u) ? (k & 0x7fffffffu) : ~k);
}

// ---------------------------------------------------------------------------
// Kernel 1: pack targets {x,y,z,-|t|^2/2}. (g_tmax arming handled by finish.)
// ---------------------------------------------------------------------------
__global__ void chamfer_prep(const float* __restrict__ tgt, int BM) {
    int i = blockIdx.x * blockDim.x + threadIdx.x;
    if (i < BM) {
        float x = tgt[3 * i], y = tgt[3 * i + 1], z = tgt[3 * i + 2];
        float k = -0.5f * (x * x + y * y + z * z);
        g_tpack[i] = make_float4(x, y, z, k);
    }
}

// ---------------------------------------------------------------------------
// Kernel 2: fused packed pass on e = s.t - |s|^2/2 - |t|^2/2 (= -d/2);
// min d (both directions) == max e. Grid (103, 8) = 824 CTAs at occupancy 6
// (24 warps/SM): raised residency to hide FFMA2/LDS/SHFL latency, at the
// cost of +7% work on the busiest SMs. Inner loop identical to R6 best.
// Block = 128 threads = 16 target-groups (tx) x 8 source-lanes (ty);
// 10 persistent sources/thread (5 packed f32x2 pairs per coordinate).
// ---------------------------------------------------------------------------
__global__ void __launch_bounds__(128, 6)
chamfer_main(const float* __restrict__ src, int N, int M) {
    const int b    = blockIdx.y;
    const int sblk = blockIdx.x;
    const int tid  = threadIdx.x;
    const int tx   = tid >> 3;    // target group 0..15
    const int ty   = tid & 7;     // source lane 0..7 (consecutive)

    __shared__ float4 stg[2][128];   // 4 KB double buffer

    // --- load 10 sources (indices clamped to batch end), pack 5 pairs -----
    const int sofs = sblk * SRCT + ty * (2 * NPP);
    const float* __restrict__ Sb = src + (size_t)b * N * 3;
    u64 sx2[NPP], sy2[NPP], sz2[NPP], sk2[NPP];
    float emax[2 * NPP];
#pragma unroll
    for (int i = 0; i < NPP; i++) {
        int i0 = min(sofs + 2 * i,     N - 1);
        int i1 = min(sofs + 2 * i + 1, N - 1);
        float x0 = Sb[3 * i0], y0 = Sb[3 * i0 + 1], z0 = Sb[3 * i0 + 2];
        float x1 = Sb[3 * i1], y1 = Sb[3 * i1 + 1], z1 = Sb[3 * i1 + 2];
        float k0 = -0.5f * (x0 * x0 + y0 * y0 + z0 * z0);
        float k1 = -0.5f * (x1 * x1 + y1 * y1 + z1 * z1);
        sx2[i] = pack2(x0, x1);
        sy2[i] = pack2(y0, y1);
        sz2[i] = pack2(z0, z1);
        sk2[i] = pack2(k0, k1);
        emax[2 * i]     = -CUDART_INF_F;
        emax[2 * i + 1] = -CUDART_INF_F;
    }

    const float4* __restrict__ T = g_tpack + (size_t)b * M;

    // Swizzle: target t stored at slot t ^ ((t>>3)&3) -> the 4 tx-quadrants
    // of a warp hit distinct 32B bank groups; 8 ty-lanes broadcast.
    const int wslot = tid ^ ((tid >> 3) & 3);
    int rs[8];
#pragma unroll
    for (int j = 0; j < 8; j++) rs[j] = tx * 8 + (j ^ (tx & 3));

    auto stage = [&](int c, int k) {
        unsigned dst = (unsigned)__cvta_generic_to_shared(&stg[k][wslot]);
        const float4* g = T + c + tid;
        asm volatile("cp.async.cg.shared.global [%0], [%1], 16;" :: "r"(dst), "l"(g));
        asm volatile("cp.async.commit_group;");
    };

    stage(0, 0);   // prologue

    for (int c = 0; c < M; c += 128) {
        const int buf = (c >> 7) & 1;

        if (c + 128 < M) {
            stage(c + 128, buf ^ 1);
            asm volatile("cp.async.wait_group 1;");
        } else {
            asm volatile("cp.async.wait_group 0;");
        }
        __syncthreads();   // current buffer visible

        float tmax[8];
#pragma unroll
        for (int j = 0; j < 8; j++) {
            float4 tv = stg[buf][rs[j]];               // LDS.128, conflict-free
            u64 tx2 = pack2(tv.x, tv.x);
            u64 ty2 = pack2(tv.y, tv.y);
            u64 tz2 = pack2(tv.z, tv.z);
            u64 tk2 = pack2(tv.w, tv.w);
            float tm = -CUDART_INF_F;
#pragma unroll
            for (int i = 0; i < NPP; i++) {
                u64 e2 = fma2_(sx2[i], tx2,
                         fma2_(sy2[i], ty2,
                         fma2_(sz2[i], tz2, add2_(sk2[i], tk2))));
                float elo, ehi;
                unpack2(e2, elo, ehi);
                emax[2 * i]     = fmaxf(emax[2 * i], elo);
                emax[2 * i + 1] = fmaxf(emax[2 * i + 1], ehi);
                tm = fmaxf(tm, fmaxf(elo, ehi));
            }
            tmax[j] = tm;
        }
        __syncthreads();   // all reads done before buffer is re-staged

        // Array-folding butterfly over the 8 ty-lanes (7 SHFL); lane ty ends
        // owning target bitrev3(ty); one spread atomic per lane.
        int own = 0, len = 8;
#pragma unroll
        for (int sft = 1; sft <= 4; sft <<= 1) {
            len >>= 1;
            const bool bit = (ty & sft) != 0;
#pragma unroll
            for (int k = 0; k < 4; k++) {
                if (k < len) {
                    float send = bit ? tmax[k] : tmax[k + len];
                    float keep = bit ? tmax[k + len] : tmax[k];
                    float recv = __shfl_xor_sync(0xffffffffu, send, sft, 8);
                    tmax[k] = fmaxf(keep, recv);
                }
            }
            if (bit) own += len;
        }
        atomicMax(&g_tmax[(size_t)b * M + c + tx * 8 + own], fenc(tmax[0]));
    }

    // Source side: max-e across the 16 tx slices, mask padded lanes, CTA sum.
    __shared__ float red[16][88];   // 80 used, padded stride
#pragma unroll
    for (int i = 0; i < 2 * NPP; i++) red[tx][ty * (2 * NPP) + i] = emax[i];
    __syncthreads();

    float contrib = 0.0f;
    if (tid < SRCT) {
        float m = red[0][tid];
#pragma unroll
        for (int k = 1; k < 16; k++) m = fmaxf(m, red[k][tid]);
        if (sblk * SRCT + tid < N) contrib = m;   // mask padded sources
    }

    __shared__ float partial[128];
    partial[tid] = contrib;
    __syncthreads();
    if (tid < 64) partial[tid] += partial[tid + 64];
    __syncthreads();
    if (tid < 32) {
        float v = partial[tid] + partial[tid + 32];
#pragma unroll
        for (int o = 16; o > 0; o >>= 1)
            v += __shfl_down_sync(0xffffffffu, v, o);
        if (tid == 0) g_ssum[b * gridDim.x + sblk] = v;  // deterministic
    }
}

// ---------------------------------------------------------------------------
// Kernel 3: deterministic final reduction; converts e-domain to distances and
// RE-ARMS g_tmax to encoded -inf for the next graph replay.
// out[b] = mean_t(-2*emax_t) + mean_s(-2*emax_s)
// ---------------------------------------------------------------------------
__global__ void chamfer_finish(float* __restrict__ out, int N, int M, int nsblk) {
    const int b   = blockIdx.x;
    const int tid = threadIdx.x;  // 256 threads
    const unsigned NEGINF = fenc(-CUDART_INF_F);

    float ts = 0.0f;
    for (int i = tid; i < M; i += 256) {
        ts += fdec(g_tmax[(size_t)b * M + i]);
        g_tmax[(size_t)b * M + i] = NEGINF;   // re-arm for next replay
    }
    float ss = 0.0f;
    for (int i = tid; i < nsblk; i += 256)
        ss += g_ssum[b * nsblk + i];

    __shared__ float s1[256], s2[256];
    s1[tid] = ts; s2[tid] = ss;
    __syncthreads();
    for (int o = 128; o > 0; o >>= 1) {
        if (tid < o) { s1[tid] += s1[tid + o]; s2[tid] += s2[tid + o]; }
        __syncthreads();
    }
    if (tid == 0) out[b] = -2.0f * (s1[0] / (float)M + s2[0] / (float)N);
}

// ---------------------------------------------------------------------------
extern "C" void kernel_launch(void* const* d_in, const int* in_sizes, int n_in,
                              void* d_out, int out_size) {
    const float* src = (const float*)d_in[0];
    const float* tgt = (const float*)d_in[1];
    float* out = (float*)d_out;

    const int B = out_size;                 // 8
    const int N = in_sizes[0] / (3 * B);    // 8192
    const int M = in_sizes[1] / (3 * B);    // 8192
    const int BM = B * M;

    chamfer_prep<<<(BM + 255) / 256, 256>>>(tgt, BM);

    dim3 grid(CPB, B);                      // 824 CTAs at occ 6: one wave
    chamfer_main<<<grid, 128>>>(src, N, M);

    chamfer_finish<<<B, 256>>>(out, N, M, CPB);
}

// round 14
// speedup vs baseline: 1.2195x; 1.2195x over previous
#include <cuda_runtime.h>
#include <math_constants.h>

// Problem constants (fixed by dataset): B=8, N=M=8192, 3-D points.
#define MAXB 8
#define MAXN 8192
#define MAXM 8192
#define CPB   74          // CTAs per batch (74*8 = 592 = 148 SMs * occ 4: one balanced wave)
#define SRCT  112         // sources per CTA tile (74*112 >= 8192; last CTA clamps indices)
#define NPP   7           // packed source-pairs per thread (14 sources / thread)

typedef unsigned long long u64;

// Static scratch (allocation-free rule).
__device__ float4       g_tpack[MAXB * MAXM];   // {x, y, z, -0.5|t|^2}
__device__ unsigned int g_tmax[MAXB * MAXM];    // encoded max-e per target (re-armed by finish)
__device__ float        g_ssum[MAXB * CPB];     // per-CTA masked source max-e sums

// ---- f32x2 packed math (FFMA2/FADD2 — PTX-only on sm_103a) --------------
__device__ __forceinline__ u64 pack2(float lo, float hi) {
    u64 r; asm("mov.b64 %0,{%1,%2};" : "=l"(r) : "f"(lo), "f"(hi)); return r;
}
__device__ __forceinline__ void unpack2(u64 v, float& lo, float& hi) {
    asm("mov.b64 {%0,%1},%2;" : "=f"(lo), "=f"(hi) : "l"(v));
}
__device__ __forceinline__ u64 fma2_(u64 a, u64 b, u64 c) {
    u64 d; asm("fma.rn.f32x2 %0,%1,%2,%3;" : "=l"(d) : "l"(a), "l"(b), "l"(c)); return d;
}
__device__ __forceinline__ u64 add2_(u64 a, u64 b) {
    u64 d; asm("add.rn.f32x2 %0,%1,%2;" : "=l"(d) : "l"(a), "l"(b)); return d;
}

// ---- monotonic float<->uint encoding (order-preserving, any sign) -------
// fenc(e) > 0 for every representable e, so the all-zero static initial
// state acts as "below -inf" for atomicMax on the first (correctness) call;
// chamfer_finish re-arms every slot to fenc(-inf) for each graph replay.
__device__ __forceinline__ unsigned fenc(float f) {
    unsigned b = __float_as_uint(f);
    return (b & 0x80000000u) ? ~b : (b | 0x80000000u);
}
__device__ __forceinline__ float fdec(unsigned k) {
    return __uint_as_float((k & 0x80000000u) ? (k & 0x7fffffffu) : ~k);
}

// ---------------------------------------------------------------------------
// Kernel 1: pack targets {x,y,z,-|t|^2/2}. (g_tmax arming handled by finish.)
// ---------------------------------------------------------------------------
__global__ void chamfer_prep(const float* __restrict__ tgt, int BM) {
    int i = blockIdx.x * blockDim.x + threadIdx.x;
    if (i < BM) {
        float x = tgt[3 * i], y = tgt[3 * i + 1], z = tgt[3 * i + 2];
        float k = -0.5f * (x * x + y * y + z * z);
        g_tpack[i] = make_float4(x, y, z, k);
    }
}

// ---------------------------------------------------------------------------
// Kernel 2: fused packed pass on e = s.t - |s|^2/2 - |t|^2/2 (= -d/2);
// min d (both directions) == max e. Grid (74, 8) = one balanced wave
// (148 SMs x occ 4). Block = 128 threads = 16 target-groups (tx) x 8
// source-lanes (ty). 14 persistent sources/thread (7 f32x2 pairs/coord) x
// 8 targets per 128-target chunk; cp.async double buffer. Identical to the
// R6 best kernel except chunk-0 staging is issued BEFORE the source-load
// prologue so the cp.async overlaps the 42 scalar LDGs.
// ---------------------------------------------------------------------------
__global__ void __launch_bounds__(128, 4)
chamfer_main(const float* __restrict__ src, int N, int M) {
    const int b    = blockIdx.y;
    const int sblk = blockIdx.x;
    const int tid  = threadIdx.x;
    const int tx   = tid >> 3;    // target group 0..15
    const int ty   = tid & 7;     // source lane 0..7 (consecutive)

    __shared__ float4 stg[2][128];   // 4 KB double buffer

    const float4* __restrict__ T = g_tpack + (size_t)b * M;

    // Swizzle: target t stored at slot t ^ ((t>>3)&3) -> the 4 tx-quadrants
    // of a warp hit distinct 32B bank groups; 8 ty-lanes broadcast.
    const int wslot = tid ^ ((tid >> 3) & 3);

    auto stage = [&](int c, int k) {
        unsigned dst = (unsigned)__cvta_generic_to_shared(&stg[k][wslot]);
        const float4* g = T + c + tid;
        asm volatile("cp.async.cg.shared.global [%0], [%1], 16;" :: "r"(dst), "l"(g));
        asm volatile("cp.async.commit_group;");
    };

    stage(0, 0);   // issued FIRST: overlaps the source-load prologue below

    // --- load 14 sources (indices clamped to batch end), pack 7 pairs -----
    const int sofs = sblk * SRCT + ty * (2 * NPP);
    const float* __restrict__ Sb = src + (size_t)b * N * 3;
    u64 sx2[NPP], sy2[NPP], sz2[NPP], sk2[NPP];
    float emax[2 * NPP];
#pragma unroll
    for (int i = 0; i < NPP; i++) {
        int i0 = min(sofs + 2 * i,     N - 1);
        int i1 = min(sofs + 2 * i + 1, N - 1);
        float x0 = Sb[3 * i0], y0 = Sb[3 * i0 + 1], z0 = Sb[3 * i0 + 2];
        float x1 = Sb[3 * i1], y1 = Sb[3 * i1 + 1], z1 = Sb[3 * i1 + 2];
        float k0 = -0.5f * (x0 * x0 + y0 * y0 + z0 * z0);
        float k1 = -0.5f * (x1 * x1 + y1 * y1 + z1 * z1);
        sx2[i] = pack2(x0, x1);
        sy2[i] = pack2(y0, y1);
        sz2[i] = pack2(z0, z1);
        sk2[i] = pack2(k0, k1);
        emax[2 * i]     = -CUDART_INF_F;
        emax[2 * i + 1] = -CUDART_INF_F;
    }

    int rs[8];
#pragma unroll
    for (int j = 0; j < 8; j++) rs[j] = tx * 8 + (j ^ (tx & 3));

    for (int c = 0; c < M; c += 128) {
        const int buf = (c >> 7) & 1;

        if (c + 128 < M) {
            stage(c + 128, buf ^ 1);
            asm volatile("cp.async.wait_group 1;");
        } else {
            asm volatile("cp.async.wait_group 0;");
        }
        __syncthreads();   // current buffer visible

        float tmax[8];
#pragma unroll
        for (int j = 0; j < 8; j++) {
            float4 tv = stg[buf][rs[j]];               // LDS.128, conflict-free
            u64 tx2 = pack2(tv.x, tv.x);
            u64 ty2 = pack2(tv.y, tv.y);
            u64 tz2 = pack2(tv.z, tv.z);
            u64 tk2 = pack2(tv.w, tv.w);
            float tm = -CUDART_INF_F;
#pragma unroll
            for (int i = 0; i < NPP; i++) {
                u64 e2 = fma2_(sx2[i], tx2,
                         fma2_(sy2[i], ty2,
                         fma2_(sz2[i], tz2, add2_(sk2[i], tk2))));
                float elo, ehi;
                unpack2(e2, elo, ehi);
                emax[2 * i]     = fmaxf(emax[2 * i], elo);
                emax[2 * i + 1] = fmaxf(emax[2 * i + 1], ehi);
                tm = fmaxf(tm, fmaxf(elo, ehi));
            }
            tmax[j] = tm;
        }
        __syncthreads();   // all reads done before buffer is re-staged

        // Array-folding butterfly over the 8 ty-lanes (7 SHFL); lane ty ends
        // owning target bitrev3(ty); one spread atomic per lane.
        int own = 0, len = 8;
#pragma unroll
        for (int sft = 1; sft <= 4; sft <<= 1) {
            len >>= 1;
            const bool bit = (ty & sft) != 0;
#pragma unroll
            for (int k = 0; k < 4; k++) {
                if (k < len) {
                    float send = bit ? tmax[k] : tmax[k + len];
                    float keep = bit ? tmax[k + len] : tmax[k];
                    float recv = __shfl_xor_sync(0xffffffffu, send, sft, 8);
                    tmax[k] = fmaxf(keep, recv);
                }
            }
            if (bit) own += len;
        }
        atomicMax(&g_tmax[(size_t)b * M + c + tx * 8 + own], fenc(tmax[0]));
    }

    // Source side: max-e across the 16 tx slices, mask padded lanes, CTA sum.
    __shared__ float red[16][120];   // 112 used, padded stride
#pragma unroll
    for (int i = 0; i < 2 * NPP; i++) red[tx][ty * (2 * NPP) + i] = emax[i];
    __syncthreads();

    float contrib = 0.0f;
    if (tid < SRCT) {
        float m = red[0][tid];
#pragma unroll
        for (int k = 1; k < 16; k++) m = fmaxf(m, red[k][tid]);
        if (sblk * SRCT + tid < N) contrib = m;   // mask padded sources
    }

    __shared__ float partial[128];
    partial[tid] = contrib;
    __syncthreads();
    if (tid < 64) partial[tid] += partial[tid + 64];
    __syncthreads();
    if (tid < 32) {
        float v = partial[tid] + partial[tid + 32];
#pragma unroll
        for (int o = 16; o > 0; o >>= 1)
            v += __shfl_down_sync(0xffffffffu, v, o);
        if (tid == 0) g_ssum[b * gridDim.x + sblk] = v;  // deterministic
    }
}

// ---------------------------------------------------------------------------
// Kernel 3: deterministic final reduction; converts e-domain to distances and
// re-arms g_tmax to encoded -inf for the next graph replay.
// out[b] = mean_t(-2*emax_t) + mean_s(-2*emax_s)
// ---------------------------------------------------------------------------
__global__ void chamfer_finish(float* __restrict__ out, int N, int M, int nsblk) {
    const int b   = blockIdx.x;
    const int tid = threadIdx.x;  // 256 threads
    const unsigned NEGINF = fenc(-CUDART_INF_F);

    float ts = 0.0f;
    for (int i = tid; i < M; i += 256) {
        ts += fdec(g_tmax[(size_t)b * M + i]);
        g_tmax[(size_t)b * M + i] = NEGINF;   // re-arm for next replay
    }
    float ss = 0.0f;
    for (int i = tid; i < nsblk; i += 256)
        ss += g_ssum[b * nsblk + i];

    __shared__ float s1[256], s2[256];
    s1[tid] = ts; s2[tid] = ss;
    __syncthreads();
    for (int o = 128; o > 0; o >>= 1) {
        if (tid < o) { s1[tid] += s1[tid + o]; s2[tid] += s2[tid + o]; }
        __syncthreads();
    }
    if (tid == 0) out[b] = -2.0f * (s1[0] / (float)M + s2[0] / (float)N);
}

// ---------------------------------------------------------------------------
extern "C" void kernel_launch(void* const* d_in, const int* in_sizes, int n_in,
                              void* d_out, int out_size) {
    const float* src = (const float*)d_in[0];
    const float* tgt = (const float*)d_in[1];
    float* out = (float*)d_out;

    const int B = out_size;                 // 8
    const int N = in_sizes[0] / (3 * B);    // 8192
    const int M = in_sizes[1] / (3 * B);    // 8192
    const int BM = B * M;

    chamfer_prep<<<(BM + 255) / 256, 256>>>(tgt, BM);

    dim3 grid(CPB, B);                      // 592 CTAs: one balanced wave
    chamfer_main<<<grid, 128>>>(src, N, M);

    chamfer_finish<<<B, 256>>>(out, N, M, CPB);
}